// round 1
// baseline (speedup 1.0000x reference)
#include <cuda_runtime.h>
#include <cuda_bf16.h>
#include <cstdint>

// Problem constants
#define BB 8
#define CC 256
#define HH 112
#define HWSZ 12544              // 112*112
#define ELEMS_PER_IMG (CC * HWSZ)       // 3,211,264
#define TOTAL_ELEMS (BB * ELEMS_PER_IMG) // 25,690,112

// Scratch (device globals; no allocations allowed)
__device__ float g_Q[TOTAL_ELEMS];
__device__ float g_K[TOTAL_ELEMS];
__device__ float g_V[TOTAL_ELEMS];
__device__ float g_Zs[TOTAL_ELEMS];

// ---------------------------------------------------------------------------
// GEMM: out[b,o,s] = sum_c W[o,c] * in[b,c,s]  (+ optional residual + relu)
// W: [256,256] row-major. in/out: [B, C, HW].
// Block tile 128x128x8, 256 threads, 8x8 per thread (split 4+4 in each dim).
// ---------------------------------------------------------------------------
__global__ void __launch_bounds__(256, 2)
gemm_conv_kernel(const float* __restrict__ Wmat,
                 const float* __restrict__ in,
                 const float* __restrict__ res,
                 float* __restrict__ out,
                 int do_relu)
{
    __shared__ float As[8][128];   // transposed W tile: As[k][m]
    __shared__ float Bs[8][128];   // Bs[k][n]

    const int b  = blockIdx.z;
    const int m0 = blockIdx.y * 128;
    const int n0 = blockIdx.x * 128;
    const float* inb  = in  + (size_t)b * ELEMS_PER_IMG;
    float*       outb = out + (size_t)b * ELEMS_PER_IMG;

    const int tid  = threadIdx.x;
    const int tRow = tid >> 4;     // 0..15
    const int tCol = tid & 15;     // 0..15

    // A load: 128x8 tile = 1024 floats; each thread: one float4
    const int aRow = tid >> 1;          // 0..127
    const int aCol = (tid & 1) * 4;     // 0 or 4
    // B load: 8x128 tile; each thread: one float4
    const int bRow = tid >> 5;          // 0..7
    const int bCol = (tid & 31) * 4;    // 0..124

    float acc[8][8];
#pragma unroll
    for (int i = 0; i < 8; i++)
#pragma unroll
        for (int j = 0; j < 8; j++) acc[i][j] = 0.0f;

    for (int kk = 0; kk < CC; kk += 8) {
        float4 av = *reinterpret_cast<const float4*>(&Wmat[(m0 + aRow) * CC + kk + aCol]);
        As[aCol + 0][aRow] = av.x;
        As[aCol + 1][aRow] = av.y;
        As[aCol + 2][aRow] = av.z;
        As[aCol + 3][aRow] = av.w;
        *reinterpret_cast<float4*>(&Bs[bRow][bCol]) =
            *reinterpret_cast<const float4*>(&inb[(size_t)(kk + bRow) * HWSZ + n0 + bCol]);
        __syncthreads();
#pragma unroll
        for (int k = 0; k < 8; ++k) {
            float a[8], bv[8];
            *reinterpret_cast<float4*>(&a[0]) = *reinterpret_cast<float4*>(&As[k][tRow * 4]);
            *reinterpret_cast<float4*>(&a[4]) = *reinterpret_cast<float4*>(&As[k][tRow * 4 + 64]);
            *reinterpret_cast<float4*>(&bv[0]) = *reinterpret_cast<float4*>(&Bs[k][tCol * 4]);
            *reinterpret_cast<float4*>(&bv[4]) = *reinterpret_cast<float4*>(&Bs[k][tCol * 4 + 64]);
#pragma unroll
            for (int i = 0; i < 8; i++)
#pragma unroll
                for (int j = 0; j < 8; j++)
                    acc[i][j] += a[i] * bv[j];
        }
        __syncthreads();
    }

    const float* resb = res ? res + (size_t)b * ELEMS_PER_IMG : nullptr;

#pragma unroll
    for (int ih = 0; ih < 2; ih++) {
#pragma unroll
        for (int i = 0; i < 4; i++) {
            const int m = m0 + tRow * 4 + ih * 64 + i;
#pragma unroll
            for (int jh = 0; jh < 2; jh++) {
                const int n = n0 + tCol * 4 + jh * 64;
                float4 v;
                v.x = acc[ih * 4 + i][jh * 4 + 0];
                v.y = acc[ih * 4 + i][jh * 4 + 1];
                v.z = acc[ih * 4 + i][jh * 4 + 2];
                v.w = acc[ih * 4 + i][jh * 4 + 3];
                if (do_relu) {
                    float4 r = *reinterpret_cast<const float4*>(&resb[(size_t)m * HWSZ + n]);
                    v.x = fmaxf(v.x + r.x, 0.0f);
                    v.y = fmaxf(v.y + r.y, 0.0f);
                    v.z = fmaxf(v.z + r.z, 0.0f);
                    v.w = fmaxf(v.w + r.w, 0.0f);
                }
                *reinterpret_cast<float4*>(&outb[(size_t)m * HWSZ + n]) = v;
            }
        }
    }
}

// ---------------------------------------------------------------------------
// Attention per (b,c): scores = Q@K -> softmax(rows) -> Z = M@V
// One block per (b,c). Q/K/V tiles (112x112 each) fully resident in smem.
// 256 threads = 16x16, each thread owns a 7x7 output micro-tile.
// Softmax row reductions via 16-lane shuffle segments.
// ---------------------------------------------------------------------------
__global__ void __launch_bounds__(256, 1)
attn_kernel(const float* __restrict__ Q, const float* __restrict__ K,
            const float* __restrict__ V, float* __restrict__ Z)
{
    extern __shared__ float sm[];
    float* Qs = sm;              // 12544 floats; reused for M, then staging is Ks
    float* Ks = sm + HWSZ;
    float* Vs = sm + 2 * HWSZ;

    const size_t base = (size_t)blockIdx.x * HWSZ;
    const int tid = threadIdx.x;

    // Coalesced float4 loads (12544/4 = 3136 per tensor)
    {
        const float4* Qg = reinterpret_cast<const float4*>(Q + base);
        const float4* Kg = reinterpret_cast<const float4*>(K + base);
        const float4* Vg = reinterpret_cast<const float4*>(V + base);
        float4* Q4 = reinterpret_cast<float4*>(Qs);
        float4* K4 = reinterpret_cast<float4*>(Ks);
        float4* V4 = reinterpret_cast<float4*>(Vs);
        for (int i = tid; i < HWSZ / 4; i += 256) {
            Q4[i] = Qg[i];
            K4[i] = Kg[i];
            V4[i] = Vg[i];
        }
    }
    __syncthreads();

    const int ty = tid >> 4;      // 0..15
    const int tx = tid & 15;      // 0..15
    const int i0 = ty * 7;
    const int j0 = tx * 7;

    float acc[7][7];
#pragma unroll
    for (int r = 0; r < 7; r++)
#pragma unroll
        for (int c = 0; c < 7; c++) acc[r][c] = 0.0f;

    // scores[i][j] = sum_k Q[i][k] * K[k][j]
    for (int k = 0; k < HH; ++k) {
        float qr[7], kc[7];
#pragma unroll
        for (int r = 0; r < 7; r++) qr[r] = Qs[(i0 + r) * HH + k];
#pragma unroll
        for (int c = 0; c < 7; c++) kc[c] = Ks[k * HH + j0 + c];
#pragma unroll
        for (int r = 0; r < 7; r++)
#pragma unroll
            for (int c = 0; c < 7; c++) acc[r][c] += qr[r] * kc[c];
    }

    // Row softmax: reduce over j (across the 16 tx lanes, which sit in a
    // 16-lane contiguous segment of the warp).
#pragma unroll
    for (int r = 0; r < 7; r++) {
        float mx = acc[r][0];
#pragma unroll
        for (int c = 1; c < 7; c++) mx = fmaxf(mx, acc[r][c]);
#pragma unroll
        for (int ofs = 1; ofs < 16; ofs <<= 1)
            mx = fmaxf(mx, __shfl_xor_sync(0xffffffffu, mx, ofs));
        float s = 0.0f;
#pragma unroll
        for (int c = 0; c < 7; c++) {
            acc[r][c] = __expf(acc[r][c] - mx);
            s += acc[r][c];
        }
#pragma unroll
        for (int ofs = 1; ofs < 16; ofs <<= 1)
            s += __shfl_xor_sync(0xffffffffu, s, ofs);
        const float inv = 1.0f / s;
#pragma unroll
        for (int c = 0; c < 7; c++) acc[r][c] *= inv;
    }

    __syncthreads();   // everyone done reading Qs before overwrite with M
#pragma unroll
    for (int r = 0; r < 7; r++)
#pragma unroll
        for (int c = 0; c < 7; c++)
            Qs[(i0 + r) * HH + j0 + c] = acc[r][c];
    __syncthreads();

    // Z = M @ V   (reuse acc registers)
#pragma unroll
    for (int r = 0; r < 7; r++)
#pragma unroll
        for (int c = 0; c < 7; c++) acc[r][c] = 0.0f;

    for (int k = 0; k < HH; ++k) {
        float mr[7], vc[7];
#pragma unroll
        for (int r = 0; r < 7; r++) mr[r] = Qs[(i0 + r) * HH + k];
#pragma unroll
        for (int c = 0; c < 7; c++) vc[c] = Vs[k * HH + j0 + c];
#pragma unroll
        for (int r = 0; r < 7; r++)
#pragma unroll
            for (int c = 0; c < 7; c++) acc[r][c] += mr[r] * vc[c];
    }

    // Stage Z through smem (Ks is dead) for coalesced global stores
    __syncthreads();
#pragma unroll
    for (int r = 0; r < 7; r++)
#pragma unroll
        for (int c = 0; c < 7; c++)
            Ks[(i0 + r) * HH + j0 + c] = acc[r][c];
    __syncthreads();
    {
        const float4* K4 = reinterpret_cast<const float4*>(Ks);
        float4* Zg = reinterpret_cast<float4*>(Z + base);
        for (int i = tid; i < HWSZ / 4; i += 256) Zg[i] = K4[i];
    }
}

extern "C" void kernel_launch(void* const* d_in, const int* in_sizes, int n_in,
                              void* d_out, int out_size)
{
    const float* x  = (const float*)d_in[0];
    const float* y  = (const float*)d_in[1];
    const float* WQ = (const float*)d_in[2];
    const float* WK = (const float*)d_in[3];
    const float* WV = (const float*)d_in[4];
    const float* WZ = (const float*)d_in[5];
    float* out = (float*)d_out;

    float *dQ, *dK, *dV, *dZ;
    cudaGetSymbolAddress((void**)&dQ, g_Q);
    cudaGetSymbolAddress((void**)&dK, g_K);
    cudaGetSymbolAddress((void**)&dV, g_V);
    cudaGetSymbolAddress((void**)&dZ, g_Zs);

    const int attn_smem = 3 * HWSZ * (int)sizeof(float);   // 150,528 B
    cudaFuncSetAttribute(attn_kernel, cudaFuncAttributeMaxDynamicSharedMemorySize,
                         attn_smem);

    dim3 gg(HWSZ / 128, CC / 128, BB);   // (98, 2, 8)

    gemm_conv_kernel<<<gg, 256>>>(WQ, x, nullptr, dQ, 0);
    gemm_conv_kernel<<<gg, 256>>>(WK, y, nullptr, dK, 0);
    gemm_conv_kernel<<<gg, 256>>>(WV, y, nullptr, dV, 0);
    attn_kernel<<<BB * CC, 256, attn_smem>>>(dQ, dK, dV, dZ);
    gemm_conv_kernel<<<gg, 256>>>(WZ, dZ, x, out, 1);
}

// round 2
// speedup vs baseline: 1.0001x; 1.0001x over previous
#include <cuda_runtime.h>
#include <cuda_bf16.h>
#include <cstdint>

// Problem constants
#define BB 8
#define CC 256
#define HH 112
#define HWSZ 12544              // 112*112
#define ELEMS_PER_IMG (CC * HWSZ)       // 3,211,264
#define TOTAL_ELEMS (BB * ELEMS_PER_IMG) // 25,690,112

// Scratch (device globals; no allocations allowed)
__device__ float g_Q[TOTAL_ELEMS];
__device__ float g_K[TOTAL_ELEMS];
__device__ float g_V[TOTAL_ELEMS];
__device__ float g_Zs[TOTAL_ELEMS];

// ---------------------------------------------------------------------------
// GEMM: out[b,o,s] = sum_c W[o,c] * in[b,c,s]  (+ optional residual + relu)
// W: [256,256] row-major. in/out: [B, C, HW].
// Block tile 128x128x8, 256 threads, 8x8 per thread (split 4+4 in each dim).
// ---------------------------------------------------------------------------
__global__ void __launch_bounds__(256, 2)
gemm_conv_kernel(const float* __restrict__ Wmat,
                 const float* __restrict__ in,
                 const float* __restrict__ res,
                 float* __restrict__ out,
                 int do_relu)
{
    __shared__ float As[8][128];   // transposed W tile: As[k][m]
    __shared__ float Bs[8][128];   // Bs[k][n]

    const int b  = blockIdx.z;
    const int m0 = blockIdx.y * 128;
    const int n0 = blockIdx.x * 128;
    const float* inb  = in  + (size_t)b * ELEMS_PER_IMG;
    float*       outb = out + (size_t)b * ELEMS_PER_IMG;

    const int tid  = threadIdx.x;
    const int tRow = tid >> 4;     // 0..15
    const int tCol = tid & 15;     // 0..15

    // A load: 128x8 tile = 1024 floats; each thread: one float4
    const int aRow = tid >> 1;          // 0..127
    const int aCol = (tid & 1) * 4;     // 0 or 4
    // B load: 8x128 tile; each thread: one float4
    const int bRow = tid >> 5;          // 0..7
    const int bCol = (tid & 31) * 4;    // 0..124

    float acc[8][8];
#pragma unroll
    for (int i = 0; i < 8; i++)
#pragma unroll
        for (int j = 0; j < 8; j++) acc[i][j] = 0.0f;

    for (int kk = 0; kk < CC; kk += 8) {
        float4 av = *reinterpret_cast<const float4*>(&Wmat[(m0 + aRow) * CC + kk + aCol]);
        As[aCol + 0][aRow] = av.x;
        As[aCol + 1][aRow] = av.y;
        As[aCol + 2][aRow] = av.z;
        As[aCol + 3][aRow] = av.w;
        *reinterpret_cast<float4*>(&Bs[bRow][bCol]) =
            *reinterpret_cast<const float4*>(&inb[(size_t)(kk + bRow) * HWSZ + n0 + bCol]);
        __syncthreads();
#pragma unroll
        for (int k = 0; k < 8; ++k) {
            float a[8], bv[8];
            *reinterpret_cast<float4*>(&a[0]) = *reinterpret_cast<float4*>(&As[k][tRow * 4]);
            *reinterpret_cast<float4*>(&a[4]) = *reinterpret_cast<float4*>(&As[k][tRow * 4 + 64]);
            *reinterpret_cast<float4*>(&bv[0]) = *reinterpret_cast<float4*>(&Bs[k][tCol * 4]);
            *reinterpret_cast<float4*>(&bv[4]) = *reinterpret_cast<float4*>(&Bs[k][tCol * 4 + 64]);
#pragma unroll
            for (int i = 0; i < 8; i++)
#pragma unroll
                for (int j = 0; j < 8; j++)
                    acc[i][j] += a[i] * bv[j];
        }
        __syncthreads();
    }

    const float* resb = res ? res + (size_t)b * ELEMS_PER_IMG : nullptr;

#pragma unroll
    for (int ih = 0; ih < 2; ih++) {
#pragma unroll
        for (int i = 0; i < 4; i++) {
            const int m = m0 + tRow * 4 + ih * 64 + i;
#pragma unroll
            for (int jh = 0; jh < 2; jh++) {
                const int n = n0 + tCol * 4 + jh * 64;
                float4 v;
                v.x = acc[ih * 4 + i][jh * 4 + 0];
                v.y = acc[ih * 4 + i][jh * 4 + 1];
                v.z = acc[ih * 4 + i][jh * 4 + 2];
                v.w = acc[ih * 4 + i][jh * 4 + 3];
                if (do_relu) {
                    float4 r = *reinterpret_cast<const float4*>(&resb[(size_t)m * HWSZ + n]);
                    v.x = fmaxf(v.x + r.x, 0.0f);
                    v.y = fmaxf(v.y + r.y, 0.0f);
                    v.z = fmaxf(v.z + r.z, 0.0f);
                    v.w = fmaxf(v.w + r.w, 0.0f);
                }
                *reinterpret_cast<float4*>(&outb[(size_t)m * HWSZ + n]) = v;
            }
        }
    }
}

// ---------------------------------------------------------------------------
// Attention per (b,c): scores = Q@K -> softmax(rows) -> Z = M@V
// One block per (b,c). Q/K/V tiles (112x112 each) fully resident in smem.
// 256 threads = 16x16, each thread owns a 7x7 output micro-tile.
// Softmax row reductions via 16-lane shuffle segments.
// ---------------------------------------------------------------------------
__global__ void __launch_bounds__(256, 1)
attn_kernel(const float* __restrict__ Q, const float* __restrict__ K,
            const float* __restrict__ V, float* __restrict__ Z)
{
    extern __shared__ float sm[];
    float* Qs = sm;              // 12544 floats; reused for M, then staging is Ks
    float* Ks = sm + HWSZ;
    float* Vs = sm + 2 * HWSZ;

    const size_t base = (size_t)blockIdx.x * HWSZ;
    const int tid = threadIdx.x;

    // Coalesced float4 loads (12544/4 = 3136 per tensor)
    {
        const float4* Qg = reinterpret_cast<const float4*>(Q + base);
        const float4* Kg = reinterpret_cast<const float4*>(K + base);
        const float4* Vg = reinterpret_cast<const float4*>(V + base);
        float4* Q4 = reinterpret_cast<float4*>(Qs);
        float4* K4 = reinterpret_cast<float4*>(Ks);
        float4* V4 = reinterpret_cast<float4*>(Vs);
        for (int i = tid; i < HWSZ / 4; i += 256) {
            Q4[i] = Qg[i];
            K4[i] = Kg[i];
            V4[i] = Vg[i];
        }
    }
    __syncthreads();

    const int ty = tid >> 4;      // 0..15
    const int tx = tid & 15;      // 0..15
    const int i0 = ty * 7;
    const int j0 = tx * 7;

    float acc[7][7];
#pragma unroll
    for (int r = 0; r < 7; r++)
#pragma unroll
        for (int c = 0; c < 7; c++) acc[r][c] = 0.0f;

    // scores[i][j] = sum_k Q[i][k] * K[k][j]
    for (int k = 0; k < HH; ++k) {
        float qr[7], kc[7];
#pragma unroll
        for (int r = 0; r < 7; r++) qr[r] = Qs[(i0 + r) * HH + k];
#pragma unroll
        for (int c = 0; c < 7; c++) kc[c] = Ks[k * HH + j0 + c];
#pragma unroll
        for (int r = 0; r < 7; r++)
#pragma unroll
            for (int c = 0; c < 7; c++) acc[r][c] += qr[r] * kc[c];
    }

    // Row softmax: reduce over j (across the 16 tx lanes, which sit in a
    // 16-lane contiguous segment of the warp).
#pragma unroll
    for (int r = 0; r < 7; r++) {
        float mx = acc[r][0];
#pragma unroll
        for (int c = 1; c < 7; c++) mx = fmaxf(mx, acc[r][c]);
#pragma unroll
        for (int ofs = 1; ofs < 16; ofs <<= 1)
            mx = fmaxf(mx, __shfl_xor_sync(0xffffffffu, mx, ofs));
        float s = 0.0f;
#pragma unroll
        for (int c = 0; c < 7; c++) {
            acc[r][c] = __expf(acc[r][c] - mx);
            s += acc[r][c];
        }
#pragma unroll
        for (int ofs = 1; ofs < 16; ofs <<= 1)
            s += __shfl_xor_sync(0xffffffffu, s, ofs);
        const float inv = 1.0f / s;
#pragma unroll
        for (int c = 0; c < 7; c++) acc[r][c] *= inv;
    }

    __syncthreads();   // everyone done reading Qs before overwrite with M
#pragma unroll
    for (int r = 0; r < 7; r++)
#pragma unroll
        for (int c = 0; c < 7; c++)
            Qs[(i0 + r) * HH + j0 + c] = acc[r][c];
    __syncthreads();

    // Z = M @ V   (reuse acc registers)
#pragma unroll
    for (int r = 0; r < 7; r++)
#pragma unroll
        for (int c = 0; c < 7; c++) acc[r][c] = 0.0f;

    for (int k = 0; k < HH; ++k) {
        float mr[7], vc[7];
#pragma unroll
        for (int r = 0; r < 7; r++) mr[r] = Qs[(i0 + r) * HH + k];
#pragma unroll
        for (int c = 0; c < 7; c++) vc[c] = Vs[k * HH + j0 + c];
#pragma unroll
        for (int r = 0; r < 7; r++)
#pragma unroll
            for (int c = 0; c < 7; c++) acc[r][c] += mr[r] * vc[c];
    }

    // Stage Z through smem (Ks is dead) for coalesced global stores
    __syncthreads();
#pragma unroll
    for (int r = 0; r < 7; r++)
#pragma unroll
        for (int c = 0; c < 7; c++)
            Ks[(i0 + r) * HH + j0 + c] = acc[r][c];
    __syncthreads();
    {
        const float4* K4 = reinterpret_cast<const float4*>(Ks);
        float4* Zg = reinterpret_cast<float4*>(Z + base);
        for (int i = tid; i < HWSZ / 4; i += 256) Zg[i] = K4[i];
    }
}

extern "C" void kernel_launch(void* const* d_in, const int* in_sizes, int n_in,
                              void* d_out, int out_size)
{
    const float* x  = (const float*)d_in[0];
    const float* y  = (const float*)d_in[1];
    const float* WQ = (const float*)d_in[2];
    const float* WK = (const float*)d_in[3];
    const float* WV = (const float*)d_in[4];
    const float* WZ = (const float*)d_in[5];
    float* out = (float*)d_out;

    float *dQ, *dK, *dV, *dZ;
    cudaGetSymbolAddress((void**)&dQ, g_Q);
    cudaGetSymbolAddress((void**)&dK, g_K);
    cudaGetSymbolAddress((void**)&dV, g_V);
    cudaGetSymbolAddress((void**)&dZ, g_Zs);

    const int attn_smem = 3 * HWSZ * (int)sizeof(float);   // 150,528 B
    cudaFuncSetAttribute(attn_kernel, cudaFuncAttributeMaxDynamicSharedMemorySize,
                         attn_smem);

    dim3 gg(HWSZ / 128, CC / 128, BB);   // (98, 2, 8)

    gemm_conv_kernel<<<gg, 256>>>(WQ, x, nullptr, dQ, 0);
    gemm_conv_kernel<<<gg, 256>>>(WK, y, nullptr, dK, 0);
    gemm_conv_kernel<<<gg, 256>>>(WV, y, nullptr, dV, 0);
    attn_kernel<<<BB * CC, 256, attn_smem>>>(dQ, dK, dV, dZ);
    gemm_conv_kernel<<<gg, 256>>>(WZ, dZ, x, out, 1);
}